// round 1
// baseline (speedup 1.0000x reference)
#include <cuda_runtime.h>
#include <cuda_bf16.h>
#include <math.h>

// Problem constants
#define HH 256
#define WW 256
#define HWSZ 65536        // 256*256
#define BB 2
#define C64 64
#define C128 128
#define C256 256

// ---------------- scratch (device globals; no allocation) ----------------
__device__ float g_up [BB * C64  * HWSZ];   // upconv output (B,64,256,256)
__device__ float g_off[BB * C256 * HWSZ];   // offset conv output (B,256,256,256)
__device__ float g_xd [BB * C128 * HWSZ];   // deform-gathered input (B,128,256,256)
__device__ float g_b1 [BB * C64  * HWSZ];   // conv1 raw output
__device__ float g_b2 [BB * C64  * HWSZ];   // conv2 raw output
__device__ float g_red[128];                // per-channel sum / sumsq
__device__ float g_ab1[128];                // BN1 scale/shift
__device__ float g_ab2[128];                // BN2 scale/shift

// ---------------- upconv (ConvTranspose2d k=2,s=2) ----------------
// up[b,o,2y+k,2x+l] = sum_i x1[b,i,y,x] * w[i,o,k,l] + bias[o]
__global__ void upconv_k(const float* __restrict__ x1, const float* __restrict__ w,
                         const float* __restrict__ bias, float* __restrict__ up)
{
    __shared__ float s_x[4][64];
    const int o = threadIdx.x;          // 0..63
    const int py = threadIdx.y;         // 0..3
    const int pix0 = blockIdx.x * 4;    // over 128*128 input pixels
    const int b = blockIdx.y;
    const int tid = py * 64 + o;
    {
        int i = tid >> 2, p = tid & 3;
        s_x[p][i] = x1[(b * 64 + i) * 16384 + pix0 + p];
    }
    __syncthreads();
    float a00 = 0.f, a01 = 0.f, a10 = 0.f, a11 = 0.f;
#pragma unroll 8
    for (int i = 0; i < 64; i++) {
        float xv = s_x[py][i];
        float4 wv = *reinterpret_cast<const float4*>(w + (i * 64 + o) * 4);
        a00 = fmaf(xv, wv.x, a00);
        a01 = fmaf(xv, wv.y, a01);
        a10 = fmaf(xv, wv.z, a10);
        a11 = fmaf(xv, wv.w, a11);
    }
    const int pix = pix0 + py;
    const int y = pix >> 7, x = pix & 127;
    const float bz = bias[o];
    float* dst = up + (b * 64 + o) * HWSZ + (2 * y) * WW + 2 * x;
    dst[0]      = a00 + bz;
    dst[1]      = a01 + bz;
    dst[WW]     = a10 + bz;
    dst[WW + 1] = a11 + bz;
}

// ---------------- generic 3x3 conv, pad 1, stride 1 ----------------
// MODE: 0 = plain input (in0, CIN channels)
//       1 = concat input: ch<64 from in0(x2), ch>=64 from in1(up)
//       2 = plain input with per-channel affine+relu applied on read (BN fusion)
// Tile: 32 out channels x (8H x 16W) pixels, 128 threads, 4oc x 8px per thread.
template<int CIN, int MODE>
__global__ void __launch_bounds__(128)
conv3x3_k(const float* __restrict__ in0, const float* __restrict__ in1,
          const float* __restrict__ wgt, const float* __restrict__ bias,
          const float* __restrict__ bnab,     // [0:64] scale, [64:128] shift (MODE 2)
          float* __restrict__ out, int cout_total)
{
    constexpr int KC = 8;
    __shared__ float s_in[KC][10][18];
    __shared__ float s_w[32][KC][9];

    const int tw = blockIdx.x * 16;
    const int th = blockIdx.y * 8;
    const int octiles = cout_total >> 5;
    const int b   = blockIdx.z / octiles;
    const int oc0 = (blockIdx.z % octiles) * 32;
    const int tid = threadIdx.x;
    const int pxg = tid & 15;
    const int ocg = tid >> 4;              // 0..7
    const int row = pxg >> 1;              // 0..7
    const int colb = (pxg & 1) * 8;        // 0 or 8

    float acc[4][8];
#pragma unroll
    for (int j = 0; j < 4; j++)
#pragma unroll
        for (int p = 0; p < 8; p++) acc[j][p] = 0.f;

#pragma unroll 1
    for (int c0 = 0; c0 < CIN; c0 += KC) {
        // ---- load input tile (KC x 10 x 18) with zero halo ----
#pragma unroll 1
        for (int idx = tid; idx < KC * 180; idx += 128) {
            int cc = idx / 180;
            int r  = (idx % 180) / 18;
            int col = idx % 18;
            int gy = th + r - 1, gx = tw + col - 1;
            float v = 0.f;
            if ((unsigned)gy < HH && (unsigned)gx < WW) {
                int ch = c0 + cc;
                const float* p;
                if (MODE == 1) {
                    p = (ch < 64) ? in0 + (b * 64 + ch) * HWSZ
                                  : in1 + (b * 64 + (ch - 64)) * HWSZ;
                } else {
                    p = in0 + (b * CIN + ch) * HWSZ;
                }
                v = p[gy * WW + gx];
                if (MODE == 2)
                    v = fmaxf(fmaf(v, bnab[ch], bnab[64 + ch]), 0.f);
            }
            s_in[cc][r][col] = v;
        }
        // ---- load weights (32 oc x KC x 9) ----
#pragma unroll 1
        for (int idx = tid; idx < 32 * KC * 9; idx += 128) {
            int j  = idx / (KC * 9);
            int rm = idx % (KC * 9);
            int cc = rm / 9, t = rm % 9;
            s_w[j][cc][t] = wgt[(size_t)(oc0 + j) * CIN * 9 + (c0 + cc) * 9 + t];
        }
        __syncthreads();

#pragma unroll 1
        for (int cc = 0; cc < KC; cc++) {
#pragma unroll
            for (int ky = 0; ky < 3; ky++) {
                float inr[10];
#pragma unroll
                for (int u = 0; u < 10; u++) inr[u] = s_in[cc][row + ky][colb + u];
#pragma unroll
                for (int kx = 0; kx < 3; kx++) {
#pragma unroll
                    for (int j = 0; j < 4; j++) {
                        float wv = s_w[ocg * 4 + j][cc][ky * 3 + kx];
#pragma unroll
                        for (int p = 0; p < 8; p++)
                            acc[j][p] = fmaf(inr[p + kx], wv, acc[j][p]);
                    }
                }
            }
        }
        __syncthreads();
    }

    // ---- write 4 oc x 8 px ----
#pragma unroll
    for (int j = 0; j < 4; j++) {
        int oc = oc0 + ocg * 4 + j;
        float bz = bias ? bias[oc] : 0.f;
        float* dst = out + (size_t)(b * cout_total + oc) * HWSZ
                         + (th + row) * WW + tw + colb;
        float4 v0 = make_float4(acc[j][0] + bz, acc[j][1] + bz, acc[j][2] + bz, acc[j][3] + bz);
        float4 v1 = make_float4(acc[j][4] + bz, acc[j][5] + bz, acc[j][6] + bz, acc[j][7] + bz);
        *reinterpret_cast<float4*>(dst)     = v0;
        *reinterpret_cast<float4*>(dst + 4) = v1;
    }
}

// ---------------- deformable bilinear gather ----------------
// off[bc,h,w,k] = offbuf[b*2C*HW + c*2HW + h*2W + 2w + k]  (flat .view reinterp)
__global__ void gather_k(const float* __restrict__ x2, const float* __restrict__ up,
                         const float* __restrict__ offs, float* __restrict__ xd)
{
    int i = blockIdx.x * blockDim.x + threadIdx.x;  // 0 .. 2^24-1
    int w = i & 255;
    int h = (i >> 8) & 255;
    int c = (i >> 16) & 127;
    int b = i >> 23;

    const float* src = (c < 64) ? x2 + (b * 64 + c) * HWSZ
                                : up + (b * 64 + (c - 64)) * HWSZ;
    int obase = b * C256 * HWSZ + c * 2 * HWSZ + h * (2 * WW) + 2 * w;
    float oy = offs[obase];
    float ox = offs[obase + 1];
    float cy = fminf(fmaxf(oy + (float)h, 0.f), 255.f);
    float cx = fminf(fmaxf(ox + (float)w, 0.f), 255.f);
    float y0f = floorf(cy), x0f = floorf(cx);
    int y0 = (int)y0f;
    int x0 = (int)x0f;
    int y1 = (int)ceilf(cy);
    int x1 = (int)ceilf(cx);
    float v00 = src[y0 * WW + x0];
    float v10 = src[y1 * WW + x0];
    float v01 = src[y0 * WW + x1];
    float v11 = src[y1 * WW + x1];
    float wy = cy - y0f, wx = cx - x0f;
    float vt = v00 + (v10 - v00) * wy;
    float vb = v01 + (v11 - v01) * wy;
    xd[i] = vt + (vb - vt) * wx;
}

// ---------------- BN statistics ----------------
__global__ void zero_red_k() { g_red[threadIdx.x] = 0.f; }

__global__ void stats_k(const float* __restrict__ buf)
{
    const int c = blockIdx.x;     // 0..63
    const int s = blockIdx.y;     // 0..7 slices over 131072 elems
    float sum = 0.f, sq = 0.f;
    for (int t = threadIdx.x; t < 16384; t += 256) {
        int e = s * 16384 + t;           // 0..131071
        int b = e >> 16;
        int r = e & 65535;
        float v = buf[(b * 64 + c) * HWSZ + r];
        sum += v;
        sq  = fmaf(v, v, sq);
    }
    __shared__ float ssum[256], ssq[256];
    int tid = threadIdx.x;
    ssum[tid] = sum; ssq[tid] = sq;
    __syncthreads();
    for (int st = 128; st > 0; st >>= 1) {
        if (tid < st) { ssum[tid] += ssum[tid + st]; ssq[tid] += ssq[tid + st]; }
        __syncthreads();
    }
    if (tid == 0) {
        atomicAdd(&g_red[c], ssum[0]);
        atomicAdd(&g_red[64 + c], ssq[0]);
    }
}

__global__ void bnfin_k(const float* __restrict__ gamma, const float* __restrict__ beta,
                        float* __restrict__ ab)
{
    int c = threadIdx.x;  // 64 threads
    const float invn = 1.f / 131072.f;
    float m = g_red[c] * invn;
    float var = fmaf(-m, m, g_red[64 + c] * invn);
    float a = gamma[c] * rsqrtf(var + 1e-5f);
    ab[c] = a;
    ab[64 + c] = fmaf(-m, a, beta[c]);
}

// ---------------- final BN+ReLU ----------------
__global__ void bnrelu_out_k(const float* __restrict__ buf, const float* __restrict__ ab,
                             float* __restrict__ out)
{
    int i = blockIdx.x * blockDim.x + threadIdx.x;  // 0 .. 2*64*HW-1
    int c = (i >> 16) & 63;
    out[i] = fmaxf(fmaf(buf[i], ab[c], ab[64 + c]), 0.f);
}

// ---------------- launch ----------------
extern "C" void kernel_launch(void* const* d_in, const int* in_sizes, int n_in,
                              void* d_out, int out_size)
{
    const float* x1   = (const float*)d_in[0];
    const float* x2   = (const float*)d_in[1];
    const float* up_w = (const float*)d_in[2];
    const float* up_b = (const float*)d_in[3];
    const float* offw = (const float*)d_in[4];
    const float* c1w  = (const float*)d_in[5];
    const float* c1b  = (const float*)d_in[6];
    const float* g1   = (const float*)d_in[7];
    const float* b1   = (const float*)d_in[8];
    const float* c2w  = (const float*)d_in[9];
    const float* c2b  = (const float*)d_in[10];
    const float* g2   = (const float*)d_in[11];
    const float* b2   = (const float*)d_in[12];
    float* outp = (float*)d_out;

    float *p_up, *p_off, *p_xd, *p_b1, *p_b2, *p_ab1, *p_ab2;
    cudaGetSymbolAddress((void**)&p_up,  g_up);
    cudaGetSymbolAddress((void**)&p_off, g_off);
    cudaGetSymbolAddress((void**)&p_xd,  g_xd);
    cudaGetSymbolAddress((void**)&p_b1,  g_b1);
    cudaGetSymbolAddress((void**)&p_b2,  g_b2);
    cudaGetSymbolAddress((void**)&p_ab1, g_ab1);
    cudaGetSymbolAddress((void**)&p_ab2, g_ab2);

    // 1) upconv
    upconv_k<<<dim3(4096, 2), dim3(64, 4)>>>(x1, up_w, up_b, p_up);

    // 2) offset conv: concat(x2, up) -> 256 channels
    conv3x3_k<128, 1><<<dim3(16, 32, 16), 128>>>(x2, p_up, offw, nullptr, nullptr,
                                                 p_off, 256);

    // 3) deformable gather
    gather_k<<<65536, 256>>>(x2, p_up, p_off, p_xd);

    // 4) conv1 (128 -> 64), raw output
    conv3x3_k<128, 0><<<dim3(16, 32, 4), 128>>>(p_xd, nullptr, c1w, c1b, nullptr,
                                                p_b1, 64);

    // 5) BN1 stats
    zero_red_k<<<1, 128>>>();
    stats_k<<<dim3(64, 8), 256>>>(p_b1);
    bnfin_k<<<1, 64>>>(g1, b1, p_ab1);

    // 6) conv2 (64 -> 64) with fused BN1+ReLU on input
    conv3x3_k<64, 2><<<dim3(16, 32, 4), 128>>>(p_b1, nullptr, c2w, c2b, p_ab1,
                                               p_b2, 64);

    // 7) BN2 stats + final BN+ReLU
    zero_red_k<<<1, 128>>>();
    stats_k<<<dim3(64, 8), 256>>>(p_b2);
    bnfin_k<<<1, 64>>>(g2, b2, p_ab2);
    bnrelu_out_k<<<32768, 256>>>(p_b2, p_ab2, outp);
}

// round 3
// speedup vs baseline: 3.7038x; 3.7038x over previous
#include <cuda_runtime.h>
#include <cuda_bf16.h>
#include <math.h>
#include <stdint.h>

#define HH 256
#define WW 256
#define HWSZ 65536
#define BB 2
#define C64 64
#define C128 128
#define C256 256

#define SW128(off) ((off) ^ (((off) >> 3) & 0x70))

__device__ __forceinline__ uint32_t smem_u32(const void* p) {
    uint32_t a;
    asm("{ .reg .u64 t; cvta.to.shared.u64 t, %1; cvt.u32.u64 %0, t; }" : "=r"(a) : "l"(p));
    return a;
}
__device__ __forceinline__ void cpa16(uint32_t dst, const void* src, int sz) {
    asm volatile("cp.async.cg.shared.global [%0], [%1], 16, %2;"
                 :: "r"(dst), "l"(src), "r"(sz) : "memory");
}
__device__ __forceinline__ void cpa_commit() {
    asm volatile("cp.async.commit_group;" ::: "memory");
}
template<int N>
__device__ __forceinline__ void cpa_wait() {
    asm volatile("cp.async.wait_group %0;" :: "n"(N) : "memory");
}
__device__ __forceinline__ void ldm_x4(uint32_t& r0, uint32_t& r1, uint32_t& r2, uint32_t& r3,
                                       uint32_t addr) {
    asm volatile("ldmatrix.sync.aligned.m8n8.x4.shared.b16 {%0,%1,%2,%3}, [%4];"
                 : "=r"(r0), "=r"(r1), "=r"(r2), "=r"(r3) : "r"(addr));
}
__device__ __forceinline__ void mma16816(float* c, const uint32_t* a, uint32_t b0, uint32_t b1) {
    asm volatile("mma.sync.aligned.m16n8k16.row.col.f32.bf16.bf16.f32 "
                 "{%0,%1,%2,%3}, {%4,%5,%6,%7}, {%8,%9}, {%0,%1,%2,%3};"
                 : "+f"(c[0]), "+f"(c[1]), "+f"(c[2]), "+f"(c[3])
                 : "r"(a[0]), "r"(a[1]), "r"(a[2]), "r"(a[3]), "r"(b0), "r"(b1));
}

// ================= scratch (device globals) =================
__device__ float g_up [BB * C64  * HWSZ];
__device__ float g_off[BB * C256 * HWSZ];
__device__ float g_b1 [BB * C64  * HWSZ];
__device__ float g_b2 [BB * C64  * HWSZ];
__device__ float g_red[128];
__device__ float g_ab1[128];
__device__ float g_ab2[128];
__device__ __nv_bfloat16 g_cat_h[BB * HWSZ * C128];
__device__ __nv_bfloat16 g_cat_l[BB * HWSZ * C128];
__device__ __nv_bfloat16 g_xd_h [BB * HWSZ * C128];
__device__ __nv_bfloat16 g_xd_l [BB * HWSZ * C128];
__device__ __nv_bfloat16 g_h1_h [BB * HWSZ * C64];
__device__ __nv_bfloat16 g_h1_l [BB * HWSZ * C64];
__device__ __nv_bfloat16 g_wo_h[18 * C256 * 64];
__device__ __nv_bfloat16 g_wo_l[18 * C256 * 64];
__device__ __nv_bfloat16 g_w1_h[18 * C64 * 64];
__device__ __nv_bfloat16 g_w1_l[18 * C64 * 64];
__device__ __nv_bfloat16 g_w2_h[9 * C64 * 64];
__device__ __nv_bfloat16 g_w2_l[9 * C64 * 64];

// ================= upconv (ConvTranspose2d k=2,s=2) =================
__global__ void upconv_k(const float* __restrict__ x1, const float* __restrict__ w,
                         const float* __restrict__ bias, float* __restrict__ up)
{
    __shared__ float s_x[4][64];
    const int o = threadIdx.x;
    const int py = threadIdx.y;
    const int pix0 = blockIdx.x * 4;
    const int b = blockIdx.y;
    const int tid = py * 64 + o;
    {
        int i = tid >> 2, p = tid & 3;
        s_x[p][i] = x1[(b * 64 + i) * 16384 + pix0 + p];
    }
    __syncthreads();
    float a00 = 0.f, a01 = 0.f, a10 = 0.f, a11 = 0.f;
#pragma unroll 8
    for (int i = 0; i < 64; i++) {
        float xv = s_x[py][i];
        float4 wv = *reinterpret_cast<const float4*>(w + (i * 64 + o) * 4);
        a00 = fmaf(xv, wv.x, a00);
        a01 = fmaf(xv, wv.y, a01);
        a10 = fmaf(xv, wv.z, a10);
        a11 = fmaf(xv, wv.w, a11);
    }
    const int pix = pix0 + py;
    const int y = pix >> 7, x = pix & 127;
    const float bz = bias[o];
    float* dst = up + (b * 64 + o) * HWSZ + (2 * y) * WW + 2 * x;
    dst[0]      = a00 + bz;
    dst[1]      = a01 + bz;
    dst[WW]     = a10 + bz;
    dst[WW + 1] = a11 + bz;
}

// ================= weight prep: (O,CIN,3,3) -> [kc][o][cc] bf16 hi/lo =================
__global__ void wprep_k(const float* __restrict__ w, __nv_bfloat16* __restrict__ wh,
                        __nv_bfloat16* __restrict__ wl, int N, int CIN)
{
    int i = blockIdx.x * blockDim.x + threadIdx.x;
    if (i >= N * CIN * 9) return;
    int t  = i % 9;
    int ci = (i / 9) % CIN;
    int o  = i / (9 * CIN);
    int q = ci >> 6, cc = ci & 63;
    int kc = t * (CIN >> 6) + q;
    float v = w[i];
    __nv_bfloat16 h = __float2bfloat16(v);
    float lo = v - __bfloat162float(h);
    int dst = (kc * N + o) * 64 + cc;
    wh[dst] = h;
    wl[dst] = __float2bfloat16(lo);
}

// ================= transpose-convert NCHW fp32 -> NHWC bf16 hi/lo =================
// MODE 0: plain. MODE 1: concat(in0, in1). MODE 2: affine+relu on read.
template<int C, int MODE>
__global__ void __launch_bounds__(256)
tc_k(const float* __restrict__ in0, const float* __restrict__ in1,
     const float* __restrict__ ab,
     __nv_bfloat16* __restrict__ oh, __nv_bfloat16* __restrict__ ol)
{
    __shared__ float s[C][33];
    const int s0 = blockIdx.x * 32;
    const int b = blockIdx.y;
    const int tid = threadIdx.x;
    const int px = tid & 31;
#pragma unroll 4
    for (int c = tid >> 5; c < C; c += 8) {
        const float* src;
        if (MODE == 1)
            src = (c < 64) ? in0 + (b * 64 + c) * HWSZ : in1 + (b * 64 + (c - 64)) * HWSZ;
        else
            src = in0 + (b * C + c) * HWSZ;
        float v = src[s0 + px];
        if (MODE == 2) v = fmaxf(fmaf(v, ab[c], ab[64 + c]), 0.f);
        s[c][px] = v;
    }
    __syncthreads();
#pragma unroll 4
    for (int e = tid; e < 32 * C; e += 256) {
        int p = e / C, c = e % C;
        float v = s[c][p];
        __nv_bfloat16 h = __float2bfloat16(v);
        float lo = v - __bfloat162float(h);
        size_t idx = ((size_t)(b * HWSZ + s0 + p)) * C + c;
        oh[idx] = h;
        ol[idx] = __float2bfloat16(lo);
    }
}

// ================= fused deformable gather + NHWC hi/lo convert =================
__global__ void __launch_bounds__(256)
gathercvt_k(const float* __restrict__ x2, const float* __restrict__ up,
            const float* __restrict__ offs,
            __nv_bfloat16* __restrict__ oh, __nv_bfloat16* __restrict__ ol)
{
    __shared__ float s[128][33];
    const int s0 = blockIdx.x * 32;
    const int b = blockIdx.y;
    const int tid = threadIdx.x;
    const int px = tid & 31;
    const int hw = s0 + px;
    const int h = hw >> 8;
    const int w = hw & 255;
#pragma unroll 4
    for (int c = tid >> 5; c < 128; c += 8) {
        const float* src = (c < 64) ? x2 + (b * 64 + c) * HWSZ
                                    : up + (b * 64 + (c - 64)) * HWSZ;
        int obase = b * C256 * HWSZ + c * 2 * HWSZ + h * (2 * WW) + 2 * w;
        float oy = offs[obase];
        float ox = offs[obase + 1];
        float cy = fminf(fmaxf(oy + (float)h, 0.f), 255.f);
        float cx = fminf(fmaxf(ox + (float)w, 0.f), 255.f);
        float y0f = floorf(cy), x0f = floorf(cx);
        int y0 = (int)y0f;
        int x0 = (int)x0f;
        int y1 = (int)ceilf(cy);
        int x1 = (int)ceilf(cx);
        float v00 = src[y0 * WW + x0];
        float v10 = src[y1 * WW + x0];
        float v01 = src[y0 * WW + x1];
        float v11 = src[y1 * WW + x1];
        float wy = cy - y0f, wx = cx - x0f;
        float vt = v00 + (v10 - v00) * wy;
        float vb = v01 + (v11 - v01) * wy;
        s[c][px] = vt + (vb - vt) * wx;
    }
    __syncthreads();
#pragma unroll 4
    for (int e = tid; e < 32 * 128; e += 256) {
        int p = e >> 7, c = e & 127;
        float v = s[c][p];
        __nv_bfloat16 hh = __float2bfloat16(v);
        float lo = v - __bfloat162float(hh);
        size_t idx = ((size_t)(b * HWSZ + s0 + p)) * 128 + c;
        oh[idx] = hh;
        ol[idx] = __float2bfloat16(lo);
    }
}

// ================= mma.sync implicit-GEMM 3x3 conv (bf16x3) =================
// A: NHWC bf16 hi/lo (CCH = (NCHUNK/9)*64 channels). B: [kc][NTOT][64] hi/lo.
// CTA: 256 thr / 8 warps. Tile M=128 pixels x N=64 outs. K chunk = 64.
// Double-buffered cp.async staging. Output: NCHW fp32 (+bias).
template<int NTOT, int NCHUNK>
__global__ void __launch_bounds__(256, 2)
convmma_k(const __nv_bfloat16* __restrict__ ah_g, const __nv_bfloat16* __restrict__ al_g,
          const __nv_bfloat16* __restrict__ bh_g, const __nv_bfloat16* __restrict__ bl_g,
          const float* __restrict__ bias, float* __restrict__ out)
{
    extern __shared__ char dsm[];
    constexpr int CINQ = NCHUNK / 9;
    constexpr int CCH  = CINQ * 64;
    constexpr int A_H = 0;           // 16K  (128 rows x 128B)
    constexpr int A_L = 16384;       // 16K
    constexpr int B_H = 32768;       // 8K   (64 rows x 128B)
    constexpr int B_L = 40960;       // 8K
    constexpr int STAGE = 49152;     // 48K per stage

    uint32_t raw = smem_u32(dsm);
    uint32_t base = (raw + 1023u) & ~1023u;
    char* smc = dsm + (base - raw);
    const int tid = threadIdx.x;
    const int wid = tid >> 5;
    const int lane = tid & 31;

    const int p0 = blockIdx.x * 128;
    const int b  = p0 >> 16;
    const int sb = p0 & 65535;
    const int y0 = sb >> 8;
    const int x0 = sb & 255;
    const int oc0 = blockIdx.y * 64;

    // ---- stager ----
    auto stage = [&](int kc, int buf) {
        const int t = kc / CINQ;
        const int q = kc - t * CINQ;
        const int ky = t / 3 - 1;
        const int kx = t % 3 - 1;
        const uint32_t sbase = base + buf * STAGE;
        const int yy = y0 + ky;
        const bool yin = (unsigned)yy < 256u;
        // A: 128 rows x 8 chunks x 2 planes
#pragma unroll
        for (int it = 0; it < 4; it++) {
            int idx = it * 256 + tid;          // 0..1023
            int m = idx >> 3, ch = idx & 7;
            int xx = x0 + m + kx;
            bool inb = yin && ((unsigned)xx < 256u);
            size_t gi = (((size_t)b << 16) + (yy << 8) + xx) * CCH + q * 64 + ch * 8;
            if (!inb) gi = 0;
            uint32_t sw = SW128(m * 128 + ch * 16);
            int sz = inb ? 16 : 0;
            cpa16(sbase + A_H + sw, ah_g + gi, sz);
            cpa16(sbase + A_L + sw, al_g + gi, sz);
        }
        // B: 64 rows x 8 chunks x 2 planes
#pragma unroll
        for (int it = 0; it < 2; it++) {
            int idx = it * 256 + tid;          // 0..511
            int o = idx >> 3, ch = idx & 7;
            size_t gi = ((size_t)kc * NTOT + oc0 + o) * 64 + ch * 8;
            uint32_t sw = SW128(o * 128 + ch * 16);
            cpa16(sbase + B_H + sw, bh_g + gi, 16);
            cpa16(sbase + B_L + sw, bl_g + gi, 16);
        }
        cpa_commit();
    };

    float acc[8][4];
#pragma unroll
    for (int g = 0; g < 8; g++)
#pragma unroll
        for (int j = 0; j < 4; j++) acc[g][j] = 0.f;

    const int mrow = wid * 16;
    stage(0, 0);

#pragma unroll 1
    for (int kc = 0; kc < NCHUNK; kc++) {
        if (kc + 1 < NCHUNK) {
            stage(kc + 1, (kc + 1) & 1);
            cpa_wait<1>();
        } else {
            cpa_wait<0>();
        }
        __syncthreads();

        const uint32_t sbase = base + (kc & 1) * STAGE;
        const uint32_t Ah = sbase + A_H, Al = sbase + A_L;
        const uint32_t Bh = sbase + B_H, Bl = sbase + B_L;
        const int arow = mrow + (lane & 15);
        const int nrow = lane & 15;
        const int chalf = (lane >> 4) * 16;    // byte offset of 8-elem half

#pragma unroll
        for (int kk = 0; kk < 4; kk++) {
            const int cb = chalf + kk * 32;    // bytes along k
            uint32_t ah[4], al[4];
            ldm_x4(ah[0], ah[1], ah[2], ah[3], Ah + SW128(arow * 128 + cb));
            ldm_x4(al[0], al[1], al[2], al[3], Al + SW128(arow * 128 + cb));
#pragma unroll
            for (int g = 0; g < 4; g++) {
                uint32_t off = SW128((g * 16 + nrow) * 128 + cb);
                uint32_t t0, t1, t2, t3, u0, u1, u2, u3;
                ldm_x4(t0, t1, t2, t3, Bh + off);
                ldm_x4(u0, u1, u2, u3, Bl + off);
                mma16816(acc[2 * g],     ah, t0, t2);
                mma16816(acc[2 * g + 1], ah, t1, t3);
                mma16816(acc[2 * g],     al, t0, t2);
                mma16816(acc[2 * g + 1], al, t1, t3);
                mma16816(acc[2 * g],     ah, u0, u2);
                mma16816(acc[2 * g + 1], ah, u1, u3);
            }
        }
        __syncthreads();
    }

    // ---- epilogue: stage [n][m] fp32 in smem, then coalesced NCHW writes ----
    float* sepi = (float*)smc;                 // 64 x 132 floats = 33.8KB
    const int em = wid * 16 + (lane >> 2);
    const int en = (lane & 3) * 2;
#pragma unroll
    for (int g = 0; g < 8; g++) {
        int n0 = g * 8 + en;
        sepi[n0 * 132 + em]           = acc[g][0];
        sepi[(n0 + 1) * 132 + em]     = acc[g][1];
        sepi[n0 * 132 + em + 8]       = acc[g][2];
        sepi[(n0 + 1) * 132 + em + 8] = acc[g][3];
    }
    __syncthreads();
#pragma unroll
    for (int j = 0; j < 8; j++) {
        int lin = j * 256 + tid;               // 0..2047
        int n = lin >> 5;
        int seg = lin & 31;
        float4 v = *(float4*)(sepi + n * 132 + seg * 4);
        float bz = bias ? bias[oc0 + n] : 0.f;
        v.x += bz; v.y += bz; v.z += bz; v.w += bz;
        *(float4*)(out + (((size_t)(b * NTOT + oc0 + n)) << 16) + sb + seg * 4) = v;
    }
}

// ================= BN statistics =================
__global__ void zero_red_k() { g_red[threadIdx.x] = 0.f; }

__global__ void stats_k(const float* __restrict__ buf)
{
    const int c = blockIdx.x;
    const int s = blockIdx.y;
    float sum = 0.f, sq = 0.f;
    for (int t = threadIdx.x; t < 16384; t += 256) {
        int e = s * 16384 + t;
        int b = e >> 16;
        int r = e & 65535;
        float v = buf[(b * 64 + c) * HWSZ + r];
        sum += v;
        sq  = fmaf(v, v, sq);
    }
    __shared__ float ssum[256], ssq[256];
    int tid = threadIdx.x;
    ssum[tid] = sum; ssq[tid] = sq;
    __syncthreads();
    for (int st = 128; st > 0; st >>= 1) {
        if (tid < st) { ssum[tid] += ssum[tid + st]; ssq[tid] += ssq[tid + st]; }
        __syncthreads();
    }
    if (tid == 0) {
        atomicAdd(&g_red[c], ssum[0]);
        atomicAdd(&g_red[64 + c], ssq[0]);
    }
}

__global__ void bnfin_k(const float* __restrict__ gamma, const float* __restrict__ beta,
                        float* __restrict__ ab)
{
    int c = threadIdx.x;
    const float invn = 1.f / 131072.f;
    float m = g_red[c] * invn;
    float var = fmaf(-m, m, g_red[64 + c] * invn);
    float a = gamma[c] * rsqrtf(var + 1e-5f);
    ab[c] = a;
    ab[64 + c] = fmaf(-m, a, beta[c]);
}

__global__ void bnrelu_out_k(const float* __restrict__ buf, const float* __restrict__ ab,
                             float* __restrict__ out)
{
    int i = blockIdx.x * blockDim.x + threadIdx.x;
    int c = (i >> 16) & 63;
    out[i] = fmaxf(fmaf(buf[i], ab[c], ab[64 + c]), 0.f);
}

// ================= launch =================
extern "C" void kernel_launch(void* const* d_in, const int* in_sizes, int n_in,
                              void* d_out, int out_size)
{
    const float* x1   = (const float*)d_in[0];
    const float* x2   = (const float*)d_in[1];
    const float* up_w = (const float*)d_in[2];
    const float* up_b = (const float*)d_in[3];
    const float* offw = (const float*)d_in[4];
    const float* c1w  = (const float*)d_in[5];
    const float* c1b  = (const float*)d_in[6];
    const float* g1   = (const float*)d_in[7];
    const float* b1   = (const float*)d_in[8];
    const float* c2w  = (const float*)d_in[9];
    const float* c2b  = (const float*)d_in[10];
    const float* g2   = (const float*)d_in[11];
    const float* b2   = (const float*)d_in[12];
    float* outp = (float*)d_out;

    float *p_up, *p_off, *p_b1, *p_b2, *p_ab1, *p_ab2;
    cudaGetSymbolAddress((void**)&p_up,  g_up);
    cudaGetSymbolAddress((void**)&p_off, g_off);
    cudaGetSymbolAddress((void**)&p_b1,  g_b1);
    cudaGetSymbolAddress((void**)&p_b2,  g_b2);
    cudaGetSymbolAddress((void**)&p_ab1, g_ab1);
    cudaGetSymbolAddress((void**)&p_ab2, g_ab2);
    __nv_bfloat16 *p_cat_h, *p_cat_l, *p_xd_h, *p_xd_l, *p_h1_h, *p_h1_l;
    __nv_bfloat16 *p_wo_h, *p_wo_l, *p_w1_h, *p_w1_l, *p_w2_h, *p_w2_l;
    cudaGetSymbolAddress((void**)&p_cat_h, g_cat_h);
    cudaGetSymbolAddress((void**)&p_cat_l, g_cat_l);
    cudaGetSymbolAddress((void**)&p_xd_h, g_xd_h);
    cudaGetSymbolAddress((void**)&p_xd_l, g_xd_l);
    cudaGetSymbolAddress((void**)&p_h1_h, g_h1_h);
    cudaGetSymbolAddress((void**)&p_h1_l, g_h1_l);
    cudaGetSymbolAddress((void**)&p_wo_h, g_wo_h);
    cudaGetSymbolAddress((void**)&p_wo_l, g_wo_l);
    cudaGetSymbolAddress((void**)&p_w1_h, g_w1_h);
    cudaGetSymbolAddress((void**)&p_w1_l, g_w1_l);
    cudaGetSymbolAddress((void**)&p_w2_h, g_w2_h);
    cudaGetSymbolAddress((void**)&p_w2_l, g_w2_l);

    const int smem_mm = 2 * 49152 + 1024;  // 99328
    cudaFuncSetAttribute(convmma_k<256, 18>, cudaFuncAttributeMaxDynamicSharedMemorySize, smem_mm);
    cudaFuncSetAttribute(convmma_k<64, 18>,  cudaFuncAttributeMaxDynamicSharedMemorySize, smem_mm);
    cudaFuncSetAttribute(convmma_k<64, 9>,   cudaFuncAttributeMaxDynamicSharedMemorySize, smem_mm);

    // 0) weight prep
    wprep_k<<<(256 * 128 * 9 + 255) / 256, 256>>>(offw, p_wo_h, p_wo_l, 256, 128);
    wprep_k<<<(64 * 128 * 9 + 255) / 256, 256>>>(c1w, p_w1_h, p_w1_l, 64, 128);
    wprep_k<<<(64 * 64 * 9 + 255) / 256, 256>>>(c2w, p_w2_h, p_w2_l, 64, 64);

    // 1) upconv
    upconv_k<<<dim3(4096, 2), dim3(64, 4)>>>(x1, up_w, up_b, p_up);

    // 2) concat -> NHWC bf16 hi/lo
    tc_k<128, 1><<<dim3(2048, 2), 256>>>(x2, p_up, nullptr, p_cat_h, p_cat_l);

    // 3) offset conv (mma.sync): N=256 via grid.y
    convmma_k<256, 18><<<dim3(1024, 4), 256, smem_mm>>>(p_cat_h, p_cat_l, p_wo_h, p_wo_l,
                                                        nullptr, p_off);

    // 4) fused gather + NHWC hi/lo
    gathercvt_k<<<dim3(2048, 2), 256>>>(x2, p_up, p_off, p_xd_h, p_xd_l);

    // 5) conv1 -> raw NCHW fp32
    convmma_k<64, 18><<<dim3(1024, 1), 256, smem_mm>>>(p_xd_h, p_xd_l, p_w1_h, p_w1_l,
                                                       c1b, p_b1);

    // 6) BN1 stats + fused affine/relu conversion
    zero_red_k<<<1, 128>>>();
    stats_k<<<dim3(64, 8), 256>>>(p_b1);
    bnfin_k<<<1, 64>>>(g1, b1, p_ab1);
    tc_k<64, 2><<<dim3(2048, 2), 256>>>(p_b1, nullptr, p_ab1, p_h1_h, p_h1_l);

    // 7) conv2 -> raw NCHW fp32
    convmma_k<64, 9><<<dim3(1024, 1), 256, smem_mm>>>(p_h1_h, p_h1_l, p_w2_h, p_w2_l,
                                                      c2b, p_b2);

    // 8) BN2 stats + final BN+ReLU
    zero_red_k<<<1, 128>>>();
    stats_k<<<dim3(64, 8), 256>>>(p_b2);
    bnfin_k<<<1, 64>>>(g2, b2, p_ab2);
    bnrelu_out_k<<<32768, 256>>>(p_b2, p_ab2, outp);
}